// round 10
// baseline (speedup 1.0000x reference)
#include <cuda_runtime.h>
#include <cuda_bf16.h>

// QuantumConv2D analytical collapse (FINAL / terminal kernel, R6-R9 confirmed):
//   out[b,c,h,w] = cos(theta[9]) * prod_{3x3 patch} cos(x[b,c,h+i,w+j])
//
// Heisenberg-picture derivation:
//   - RY(theta_q), q != 9, commute with Z_9 and cancel with their daggers.
//   - RY(t9)^dag Z RY(t9) = cos(t9) Z - sin(t9) X
//   - CNOT chain (q -> q+1) pulls Z_9 back to Z_0...Z_9 ; X_9 is invariant.
//   - Product state: <Z_q> = cos(a_q), <X_9> = sin(0) = 0, ancilla factor cos(0)=1.
//
// Terminal evidence (9 rounds):
//   - Identical binary benched {6.624, 6.624, 6.656, 6.656}us -> intrinsic
//     noise = one 32ns timer tick; benched time is the graph-replay +
//     launch-ramp overhead constant. R1's kernel was 2.6us slower under
//     locked clocks and benched identically -> kernel body has no measurable
//     weight in the benched number.
//   - All pipes <6% busy in every profile (DRAM 2.3%, fma 2.5%).
//   - Falsified/rejected: 2-out/thr (R3 regression: warp count is the binding
//     latency-hiding resource), CTA reshapes (R5 null), smem amortization
//     (R1 null), hoisting (R6 null), shuffle/float4 reuse (issue non-binding;
//     requires the warp-for-work trade R3 falsified).
// Final shape: 1 output/thread, 768 CTAs x 256 thr (one wave, ~39 warps/SM),
//   shift/and-only indexing, 9 back-to-back LDG (MLP=9), 10 MUFU.COS,
//   balanced product tree, 1 STG. regs=21, no smem, no syncs.

#define IMG_H 64
#define IMG_W 64
#define OUT_H 62
#define OUT_W 62

__global__ __launch_bounds__(256)
void qconv3x3_coscos_kernel(const float* __restrict__ x,
                            const float* __restrict__ theta,
                            float* __restrict__ out)
{
    // Hoist theta load first: its LDG + MUFU overlap the pixel-load window.
    const float t9 = __ldg(&theta[9]);

    const unsigned tid = threadIdx.x;
    const unsigned r   = (blockIdx.x << 2) + (tid >> 6);   // 0..63
    const unsigned c   = tid & 63;                         // 0..63
    if (r >= OUT_H || c >= OUT_W) return;

    const unsigned bc = blockIdx.y;                        // 0..47
    const float* p = x + ((bc << 12) | (r << 6) | c);      // bc*4096 + r*64 + c

    // 9 independent loads first (max MLP), then MUFU, then product tree.
    const float a0 = p[0],            a1 = p[1],             a2 = p[2];
    const float a3 = p[IMG_W],        a4 = p[IMG_W + 1],     a5 = p[IMG_W + 2];
    const float a6 = p[2 * IMG_W],    a7 = p[2 * IMG_W + 1], a8 = p[2 * IMG_W + 2];

    const float cT = __cosf(t9);
    const float c0 = __cosf(a0), c1 = __cosf(a1), c2 = __cosf(a2);
    const float c3 = __cosf(a3), c4 = __cosf(a4), c5 = __cosf(a5);
    const float c6 = __cosf(a6), c7 = __cosf(a7), c8 = __cosf(a8);

    const float p01 = c0 * c1, p23 = c2 * c3, p45 = c4 * c5, p67 = c6 * c7;
    const float prod = ((p01 * p23) * (p45 * p67)) * (c8 * cT);

    out[bc * (OUT_H * OUT_W) + r * OUT_W + c] = prod;
}

extern "C" void kernel_launch(void* const* d_in, const int* in_sizes, int n_in,
                              void* d_out, int out_size)
{
    const float* x     = (const float*)d_in[0];   // [16,3,64,64] float32
    const float* theta = (const float*)d_in[1];   // [10] float32
    float* out = (float*)d_out;                   // [16,3,62,62] float32

    dim3 grid(16, 48);                            // 768 CTAs x 256 threads
    qconv3x3_coscos_kernel<<<grid, 256>>>(x, theta, out);
}

// round 11
// speedup vs baseline: 1.0385x; 1.0385x over previous
#include <cuda_runtime.h>
#include <cuda_bf16.h>

// QuantumConv2D analytical collapse (FINAL / terminal kernel, R6-R10 confirmed):
//   out[b,c,h,w] = cos(theta[9]) * prod_{3x3 patch} cos(x[b,c,h+i,w+j])
//
// Heisenberg-picture derivation:
//   - RY(theta_q), q != 9, commute with Z_9 and cancel with their daggers.
//   - RY(t9)^dag Z RY(t9) = cos(t9) Z - sin(t9) X
//   - CNOT chain (q -> q+1) pulls Z_9 back to Z_0...Z_9 ; X_9 is invariant.
//   - Product state: <Z_q> = cos(a_q), <X_9> = sin(0) = 0, ancilla factor cos(0)=1.
//
// Terminal evidence (10 rounds):
//   - Identical binary benched {6.624, 6.624, 6.656, 6.656, 6.912}us ->
//     same-binary noise spans ~0.3us; NO variant across ten rounds produced
//     a bench delta distinguishable from this noise (even R1, 2.6us slower
//     under locked clocks, benched inside the band). Benched time is the
//     graph-replay + launch-ramp overhead constant.
//   - All pipes <6% busy in every profile (DRAM ~2.2%, fma ~2.5%); the chip
//     is >94% idle on every axis — no binding resource exists for a .cu edit.
//   - Explored: smem amortization (R1), 1-out/thr grids (R2/R4/R5/R6),
//     2-out/thr (R3), CTA reshapes, hoisting — all bench-equivalent.
// Final shape: 1 output/thread, 768 CTAs x 256 thr (one wave, ~39 warps/SM),
//   shift/and-only indexing, 9 back-to-back LDG (MLP=9), 10 MUFU.COS,
//   balanced product tree, 1 STG. regs=21, no smem, no syncs.

#define IMG_H 64
#define IMG_W 64
#define OUT_H 62
#define OUT_W 62

__global__ __launch_bounds__(256)
void qconv3x3_coscos_kernel(const float* __restrict__ x,
                            const float* __restrict__ theta,
                            float* __restrict__ out)
{
    // Hoist theta load first: its LDG + MUFU overlap the pixel-load window.
    const float t9 = __ldg(&theta[9]);

    const unsigned tid = threadIdx.x;
    const unsigned r   = (blockIdx.x << 2) + (tid >> 6);   // 0..63
    const unsigned c   = tid & 63;                         // 0..63
    if (r >= OUT_H || c >= OUT_W) return;

    const unsigned bc = blockIdx.y;                        // 0..47
    const float* p = x + ((bc << 12) | (r << 6) | c);      // bc*4096 + r*64 + c

    // 9 independent loads first (max MLP), then MUFU, then product tree.
    const float a0 = p[0],            a1 = p[1],             a2 = p[2];
    const float a3 = p[IMG_W],        a4 = p[IMG_W + 1],     a5 = p[IMG_W + 2];
    const float a6 = p[2 * IMG_W],    a7 = p[2 * IMG_W + 1], a8 = p[2 * IMG_W + 2];

    const float cT = __cosf(t9);
    const float c0 = __cosf(a0), c1 = __cosf(a1), c2 = __cosf(a2);
    const float c3 = __cosf(a3), c4 = __cosf(a4), c5 = __cosf(a5);
    const float c6 = __cosf(a6), c7 = __cosf(a7), c8 = __cosf(a8);

    const float p01 = c0 * c1, p23 = c2 * c3, p45 = c4 * c5, p67 = c6 * c7;
    const float prod = ((p01 * p23) * (p45 * p67)) * (c8 * cT);

    out[bc * (OUT_H * OUT_W) + r * OUT_W + c] = prod;
}

extern "C" void kernel_launch(void* const* d_in, const int* in_sizes, int n_in,
                              void* d_out, int out_size)
{
    const float* x     = (const float*)d_in[0];   // [16,3,64,64] float32
    const float* theta = (const float*)d_in[1];   // [10] float32
    float* out = (float*)d_out;                   // [16,3,62,62] float32

    dim3 grid(16, 48);                            // 768 CTAs x 256 threads
    qconv3x3_coscos_kernel<<<grid, 256>>>(x, theta, out);
}

// round 12
// speedup vs baseline: 1.0435x; 1.0048x over previous
#include <cuda_runtime.h>
#include <cuda_bf16.h>

// QuantumConv2D analytical collapse (FINAL / terminal kernel, R6-R11 confirmed):
//   out[b,c,h,w] = cos(theta[9]) * prod_{3x3 patch} cos(x[b,c,h+i,w+j])
//
// Heisenberg-picture derivation:
//   - RY(theta_q), q != 9, commute with Z_9 and cancel with their daggers.
//   - RY(t9)^dag Z RY(t9) = cos(t9) Z - sin(t9) X
//   - CNOT chain (q -> q+1) pulls Z_9 back to Z_0...Z_9 ; X_9 is invariant.
//   - Product state: <Z_q> = cos(a_q), <X_9> = sin(0) = 0, ancilla factor cos(0)=1.
//
// Terminal evidence (11 rounds):
//   - Identical binary benched {6.624, 6.624, 6.656, 6.656, 6.656, 6.912}us
//     (median 6.656): same-binary noise ~0.3us span. No variant across all
//     rounds produced a bench delta outside this band — including R1, whose
//     kernel was 2.6us slower under locked clocks. Benched time = graph-replay
//     + launch-ramp overhead constant (harness floor).
//   - Every profile: all pipes <6% (DRAM ~2.2%, fma ~2.5%) — no binding
//     resource exists for any .cu edit to relieve.
//   - Explored bench-equivalent: smem 2-phase, 1-out/thr x3 grid geometries,
//     2-out/thr vectorized, CTA halving, hoisting. Rejected analytically:
//     float4 (alignment), shuffle reuse (issue non-binding + SHFL latency).
// Final shape: 1 output/thread, 768 CTAs x 256 thr (one wave, ~39 warps/SM),
//   shift/and-only indexing, 9 back-to-back LDG (MLP=9), 10 MUFU.COS,
//   balanced product tree, 1 STG. regs=21, no smem, no syncs.

#define IMG_H 64
#define IMG_W 64
#define OUT_H 62
#define OUT_W 62

__global__ __launch_bounds__(256)
void qconv3x3_coscos_kernel(const float* __restrict__ x,
                            const float* __restrict__ theta,
                            float* __restrict__ out)
{
    // Hoist theta load first: its LDG + MUFU overlap the pixel-load window.
    const float t9 = __ldg(&theta[9]);

    const unsigned tid = threadIdx.x;
    const unsigned r   = (blockIdx.x << 2) + (tid >> 6);   // 0..63
    const unsigned c   = tid & 63;                         // 0..63
    if (r >= OUT_H || c >= OUT_W) return;

    const unsigned bc = blockIdx.y;                        // 0..47
    const float* p = x + ((bc << 12) | (r << 6) | c);      // bc*4096 + r*64 + c

    // 9 independent loads first (max MLP), then MUFU, then product tree.
    const float a0 = p[0],            a1 = p[1],             a2 = p[2];
    const float a3 = p[IMG_W],        a4 = p[IMG_W + 1],     a5 = p[IMG_W + 2];
    const float a6 = p[2 * IMG_W],    a7 = p[2 * IMG_W + 1], a8 = p[2 * IMG_W + 2];

    const float cT = __cosf(t9);
    const float c0 = __cosf(a0), c1 = __cosf(a1), c2 = __cosf(a2);
    const float c3 = __cosf(a3), c4 = __cosf(a4), c5 = __cosf(a5);
    const float c6 = __cosf(a6), c7 = __cosf(a7), c8 = __cosf(a8);

    const float p01 = c0 * c1, p23 = c2 * c3, p45 = c4 * c5, p67 = c6 * c7;
    const float prod = ((p01 * p23) * (p45 * p67)) * (c8 * cT);

    out[bc * (OUT_H * OUT_W) + r * OUT_W + c] = prod;
}

extern "C" void kernel_launch(void* const* d_in, const int* in_sizes, int n_in,
                              void* d_out, int out_size)
{
    const float* x     = (const float*)d_in[0];   // [16,3,64,64] float32
    const float* theta = (const float*)d_in[1];   // [10] float32
    float* out = (float*)d_out;                   // [16,3,62,62] float32

    dim3 grid(16, 48);                            // 768 CTAs x 256 threads
    qconv3x3_coscos_kernel<<<grid, 256>>>(x, theta, out);
}

// round 13
// speedup vs baseline: 1.0854x; 1.0402x over previous
#include <cuda_runtime.h>
#include <cuda_bf16.h>

// QuantumConv2D analytical collapse (FINAL / terminal kernel, R6-R12 confirmed):
//   out[b,c,h,w] = cos(theta[9]) * prod_{3x3 patch} cos(x[b,c,h+i,w+j])
//
// Heisenberg-picture derivation:
//   - RY(theta_q), q != 9, commute with Z_9 and cancel with their daggers.
//   - RY(t9)^dag Z RY(t9) = cos(t9) Z - sin(t9) X
//   - CNOT chain (q -> q+1) pulls Z_9 back to Z_0...Z_9 ; X_9 is invariant.
//   - Product state: <Z_q> = cos(a_q), <X_9> = sin(0) = 0, ancilla factor cos(0)=1.
//
// Terminal evidence (12 rounds):
//   - Identical binary benched {6.624 x3, 6.656 x3, 6.912 x1}us: stable
//     tick distribution, median 6.656. No variant in twelve rounds produced
//     a bench delta outside this same-binary band — including R1, whose
//     kernel was 2.6us slower under locked clocks. Benched time = graph-replay
//     + launch-ramp overhead constant (harness floor).
//   - Twelve profiles: every pipe <6% (DRAM ~2.2%, fma ~2.5%) — the chip is
//     >94% idle on all axes; no binding resource exists for a .cu edit.
//   - Explored bench-equivalent: smem 2-phase, 1-out/thr x3 grid geometries,
//     2-out/thr vectorized, CTA halving, hoisting. Rejected analytically:
//     float4 (alignment), shuffle reuse (issue non-binding + SHFL latency).
// Final shape: 1 output/thread, 768 CTAs x 256 thr (one wave, ~39 warps/SM),
//   shift/and-only indexing, 9 back-to-back LDG (MLP=9), 10 MUFU.COS,
//   balanced product tree, 1 STG. regs=21, no smem, no syncs.

#define IMG_H 64
#define IMG_W 64
#define OUT_H 62
#define OUT_W 62

__global__ __launch_bounds__(256)
void qconv3x3_coscos_kernel(const float* __restrict__ x,
                            const float* __restrict__ theta,
                            float* __restrict__ out)
{
    // Hoist theta load first: its LDG + MUFU overlap the pixel-load window.
    const float t9 = __ldg(&theta[9]);

    const unsigned tid = threadIdx.x;
    const unsigned r   = (blockIdx.x << 2) + (tid >> 6);   // 0..63
    const unsigned c   = tid & 63;                         // 0..63
    if (r >= OUT_H || c >= OUT_W) return;

    const unsigned bc = blockIdx.y;                        // 0..47
    const float* p = x + ((bc << 12) | (r << 6) | c);      // bc*4096 + r*64 + c

    // 9 independent loads first (max MLP), then MUFU, then product tree.
    const float a0 = p[0],            a1 = p[1],             a2 = p[2];
    const float a3 = p[IMG_W],        a4 = p[IMG_W + 1],     a5 = p[IMG_W + 2];
    const float a6 = p[2 * IMG_W],    a7 = p[2 * IMG_W + 1], a8 = p[2 * IMG_W + 2];

    const float cT = __cosf(t9);
    const float c0 = __cosf(a0), c1 = __cosf(a1), c2 = __cosf(a2);
    const float c3 = __cosf(a3), c4 = __cosf(a4), c5 = __cosf(a5);
    const float c6 = __cosf(a6), c7 = __cosf(a7), c8 = __cosf(a8);

    const float p01 = c0 * c1, p23 = c2 * c3, p45 = c4 * c5, p67 = c6 * c7;
    const float prod = ((p01 * p23) * (p45 * p67)) * (c8 * cT);

    out[bc * (OUT_H * OUT_W) + r * OUT_W + c] = prod;
}

extern "C" void kernel_launch(void* const* d_in, const int* in_sizes, int n_in,
                              void* d_out, int out_size)
{
    const float* x     = (const float*)d_in[0];   // [16,3,64,64] float32
    const float* theta = (const float*)d_in[1];   // [10] float32
    float* out = (float*)d_out;                   // [16,3,62,62] float32

    dim3 grid(16, 48);                            // 768 CTAs x 256 threads
    qconv3x3_coscos_kernel<<<grid, 256>>>(x, theta, out);
}